// round 1
// baseline (speedup 1.0000x reference)
#include <cuda_runtime.h>
#include <cuda_bf16.h>
#include <math.h>

// Problem constants
#define BB   2
#define SS   2048
#define MM   512
#define DD   1024
#define HH   16
#define HD   64
#define NTOK (BB*SS)        // 4096
#define MTOK (BB*MM)        // 1024
#define FF   4096           // 4*D

// ---------------- scratch (device globals; no allocation) ----------------
__device__ float g_h   [NTOK*DD];
__device__ float g_tq  [NTOK*32];
__device__ float g_q   [NTOK*DD];
__device__ float g_ckv [NTOK*64];
__device__ float g_k   [NTOK*DD];
__device__ float g_v   [NTOK*DD];
__device__ float g_o   [NTOK*DD];
__device__ float g_x1  [NTOK*DD];
__device__ float g_h2  [NTOK*DD];
__device__ float g_qc  [NTOK*DD];
__device__ float g_kc  [MTOK*DD];
__device__ float g_vc  [MTOK*DD];
__device__ float g_oc  [NTOK*DD];
__device__ float g_x2  [NTOK*DD];
__device__ float g_h3  [NTOK*DD];
__device__ float g_gate[NTOK*FF];
__device__ float g_up  [NTOK*FF];

// ---------------- rmsnorm ----------------
__global__ void rmsnorm_kernel(const float* __restrict__ x, const float* __restrict__ w,
                               float* __restrict__ out, int D) {
    int row = blockIdx.x;
    const float* xr = x + (size_t)row * D;
    __shared__ float red[256];
    float s = 0.f;
    for (int i = threadIdx.x; i < D; i += 256) { float v = xr[i]; s += v * v; }
    red[threadIdx.x] = s; __syncthreads();
    for (int st = 128; st > 0; st >>= 1) {
        if (threadIdx.x < st) red[threadIdx.x] += red[threadIdx.x + st];
        __syncthreads();
    }
    float inv = rsqrtf(red[0] / (float)D + 1e-6f);
    for (int i = threadIdx.x; i < D; i += 256)
        out[(size_t)row * D + i] = xr[i] * inv * w[i];
}

// ---------------- SGEMM: C = A[MxK] @ B[KxN] (+ R) ----------------
#define BM 64
#define BN 64
#define BK 16
__global__ void sgemm_kernel(const float* __restrict__ A, const float* __restrict__ B,
                             const float* __restrict__ R, float* __restrict__ C,
                             int M, int N, int K) {
    __shared__ float As[BK][BM + 4];
    __shared__ float Bs[BK][BN + 4];
    int tid = threadIdx.x;
    int tx = tid % 16, ty = tid / 16;
    int bm = blockIdx.y * BM, bn = blockIdx.x * BN;

    float acc[4][4] = {};

    int arow  = tid / 4;          // 0..63
    int acol4 = (tid % 4) * 4;    // 0,4,8,12
    int brow  = tid / 16;         // 0..15
    int bcol4 = (tid % 16) * 4;   // 0..60

    for (int k0 = 0; k0 < K; k0 += BK) {
        {
            int gr = bm + arow;
            #pragma unroll
            for (int kk = 0; kk < 4; kk++) {
                int gk = k0 + acol4 + kk;
                float vv = 0.f;
                if (gr < M && gk < K) vv = A[(size_t)gr * K + gk];
                As[acol4 + kk][arow] = vv;
            }
        }
        {
            int gk = k0 + brow;
            #pragma unroll
            for (int nn = 0; nn < 4; nn++) {
                int gn = bn + bcol4 + nn;
                float vv = 0.f;
                if (gk < K && gn < N) vv = B[(size_t)gk * N + gn];
                Bs[brow][bcol4 + nn] = vv;
            }
        }
        __syncthreads();
        #pragma unroll
        for (int k = 0; k < BK; k++) {
            float ra[4], rb[4];
            #pragma unroll
            for (int i = 0; i < 4; i++) ra[i] = As[k][ty * 4 + i];
            #pragma unroll
            for (int j = 0; j < 4; j++) rb[j] = Bs[k][tx * 4 + j];
            #pragma unroll
            for (int i = 0; i < 4; i++)
                #pragma unroll
                for (int j = 0; j < 4; j++)
                    acc[i][j] += ra[i] * rb[j];
        }
        __syncthreads();
    }
    #pragma unroll
    for (int i = 0; i < 4; i++) {
        int gr = bm + ty * 4 + i;
        if (gr >= M) continue;
        #pragma unroll
        for (int j = 0; j < 4; j++) {
            int gn = bn + tx * 4 + j;
            if (gn >= N) continue;
            float vv = acc[i][j];
            if (R) vv += R[(size_t)gr * N + gn];
            C[(size_t)gr * N + gn] = vv;
        }
    }
}

// ---------------- self attention (flash-style, fp32) ----------------
// grid: (S/64, H, B), block 256, dynamic smem
__global__ void self_attn_kernel(const float* __restrict__ q, const float* __restrict__ k,
                                 const float* __restrict__ v, float* __restrict__ o) {
    extern __shared__ float sm[];
    float* Qs = sm;                 // [64][65]
    float* Ks = Qs + 64 * 65;       // [64][65]
    float* Vs = Ks + 64 * 65;       // [64][65]
    float* Ps = Vs + 64 * 65;       // [64][65]
    float* row_max  = Ps + 64 * 65; // [64]
    float* row_sum  = row_max + 64; // [64]
    float* row_corr = row_sum + 64; // [64]

    int qt = blockIdx.x, h = blockIdx.y, b = blockIdx.z;
    int q0 = qt * 64;
    int tid = threadIdx.x;
    int tx = tid % 16, ty = tid / 16;

    for (int idx = tid; idx < 64 * 64; idx += 256) {
        int r = idx / 64, c = idx % 64;
        Qs[r * 65 + c] = q[((size_t)(b * SS + q0 + r)) * DD + h * HD + c] * 0.125f;
    }
    if (tid < 64) { row_max[tid] = -INFINITY; row_sum[tid] = 0.f; }
    float acc[4][4] = {};
    __syncthreads();

    for (int jt = 0; jt <= qt; jt++) {
        int kv0 = jt * 64;
        for (int idx = tid; idx < 64 * 64; idx += 256) {
            int r = idx / 64, c = idx % 64;
            size_t base = ((size_t)(b * SS + kv0 + r)) * DD + h * HD + c;
            Ks[r * 65 + c] = k[base];
            Vs[r * 65 + c] = v[base];
        }
        __syncthreads();

        // S = Q @ K^T
        float sacc[4][4] = {};
        #pragma unroll 4
        for (int kk = 0; kk < 64; kk++) {
            float ra[4], rb[4];
            #pragma unroll
            for (int i = 0; i < 4; i++) ra[i] = Qs[(ty * 4 + i) * 65 + kk];
            #pragma unroll
            for (int j = 0; j < 4; j++) rb[j] = Ks[(tx * 4 + j) * 65 + kk];
            #pragma unroll
            for (int i = 0; i < 4; i++)
                #pragma unroll
                for (int j = 0; j < 4; j++)
                    sacc[i][j] += ra[i] * rb[j];
        }
        bool diag = (jt == qt);
        #pragma unroll
        for (int i = 0; i < 4; i++)
            #pragma unroll
            for (int j = 0; j < 4; j++) {
                int r = ty * 4 + i, c = tx * 4 + j;
                float sv = sacc[i][j];
                if (diag && (kv0 + c > q0 + r)) sv = -INFINITY;
                Ps[r * 65 + c] = sv;
            }
        __syncthreads();

        // online softmax per row
        if (tid < 64) {
            float m = row_max[tid];
            float tm = -INFINITY;
            for (int c = 0; c < 64; c++) tm = fmaxf(tm, Ps[tid * 65 + c]);
            float nm = fmaxf(m, tm);
            float corr = __expf(m - nm);
            float s = 0.f;
            for (int c = 0; c < 64; c++) {
                float p = __expf(Ps[tid * 65 + c] - nm);
                Ps[tid * 65 + c] = p;
                s += p;
            }
            row_sum[tid]  = row_sum[tid] * corr + s;
            row_max[tid]  = nm;
            row_corr[tid] = corr;
        }
        __syncthreads();

        // acc = acc*corr + P @ V
        float pacc[4][4] = {};
        #pragma unroll 4
        for (int kk = 0; kk < 64; kk++) {
            float rp[4], rv[4];
            #pragma unroll
            for (int i = 0; i < 4; i++) rp[i] = Ps[(ty * 4 + i) * 65 + kk];
            #pragma unroll
            for (int j = 0; j < 4; j++) rv[j] = Vs[kk * 65 + tx * 4 + j];
            #pragma unroll
            for (int i = 0; i < 4; i++)
                #pragma unroll
                for (int j = 0; j < 4; j++)
                    pacc[i][j] += rp[i] * rv[j];
        }
        #pragma unroll
        for (int i = 0; i < 4; i++) {
            float cc = row_corr[ty * 4 + i];
            #pragma unroll
            for (int j = 0; j < 4; j++)
                acc[i][j] = acc[i][j] * cc + pacc[i][j];
        }
        __syncthreads();
    }

    #pragma unroll
    for (int i = 0; i < 4; i++) {
        int r = ty * 4 + i;
        float inv = 1.f / row_sum[r];
        #pragma unroll
        for (int j = 0; j < 4; j++) {
            int c = tx * 4 + j;
            o[((size_t)(b * SS + q0 + r)) * DD + h * HD + c] = acc[i][j] * inv;
        }
    }
}

// ---------------- cross attention (windowed, <=9 keys) ----------------
// grid: (NTOK, 4), block 128 (4 warps = 4 heads)
__global__ void cross_attn_kernel(const float* __restrict__ qc, const float* __restrict__ kc,
                                  const float* __restrict__ vc, const int* __restrict__ seg_ids,
                                  float* __restrict__ oc) {
    int n = blockIdx.x;
    int warp = threadIdx.x / 32;
    int lane = threadIdx.x % 32;
    int h = blockIdx.y * 4 + warp;
    int b = n / SS;
    int seg = seg_ids[n];
    int jlo = seg - 8; if (jlo < 0) jlo = 0;
    int cnt = seg - jlo + 1;

    const float* qv = qc + (size_t)n * DD + h * HD;
    float q0v = qv[lane], q1v = qv[lane + 32];

    float sc[9];
    float mx = -INFINITY;
    for (int t = 0; t < cnt; t++) {
        const float* kv = kc + ((size_t)(b * MM + jlo + t)) * DD + h * HD;
        float p = q0v * kv[lane] + q1v * kv[lane + 32];
        #pragma unroll
        for (int off = 16; off > 0; off >>= 1)
            p += __shfl_xor_sync(0xffffffff, p, off);
        p *= 0.125f;
        sc[t] = p;
        mx = fmaxf(mx, p);
    }
    float sum = 0.f;
    for (int t = 0; t < cnt; t++) { sc[t] = __expf(sc[t] - mx); sum += sc[t]; }
    float o0 = 0.f, o1 = 0.f;
    for (int t = 0; t < cnt; t++) {
        const float* vv = vc + ((size_t)(b * MM + jlo + t)) * DD + h * HD;
        o0 += sc[t] * vv[lane];
        o1 += sc[t] * vv[lane + 32];
    }
    float inv = 1.f / sum;
    oc[(size_t)n * DD + h * HD + lane]      = o0 * inv;
    oc[(size_t)n * DD + h * HD + lane + 32] = o1 * inv;
}

// ---------------- silu(g)*u ----------------
__global__ void silu_mul_kernel(float* __restrict__ g, const float* __restrict__ u, int n) {
    int i = blockIdx.x * blockDim.x + threadIdx.x;
    if (i < n) {
        float gv = g[i];
        float s = gv / (1.f + __expf(-gv));
        g[i] = s * u[i];
    }
}

// ---------------- launch ----------------
static inline dim3 gemm_grid(int M, int N) { return dim3((N + BN - 1) / BN, (M + BM - 1) / BM); }

extern "C" void kernel_launch(void* const* d_in, const int* in_sizes, int n_in,
                              void* d_out, int out_size) {
    const float* x        = (const float*)d_in[0];
    const float* memory   = (const float*)d_in[1];
    const int*   seg_ids  = (const int*)  d_in[2];
    const float* norm1_w  = (const float*)d_in[3];
    const float* W_dq     = (const float*)d_in[4];
    const float* W_uq     = (const float*)d_in[5];
    const float* W_dkv    = (const float*)d_in[6];
    const float* W_uk     = (const float*)d_in[7];
    const float* W_uv     = (const float*)d_in[8];
    const float* W_o_self = (const float*)d_in[9];
    const float* norm2_w  = (const float*)d_in[10];
    const float* W_q_c    = (const float*)d_in[11];
    const float* W_k_c    = (const float*)d_in[12];
    const float* W_v_c    = (const float*)d_in[13];
    const float* W_o_c    = (const float*)d_in[14];
    const float* norm3_w  = (const float*)d_in[15];
    const float* W_gate   = (const float*)d_in[16];
    const float* W_up     = (const float*)d_in[17];
    const float* W_down   = (const float*)d_in[18];
    float* out = (float*)d_out;

    float *h, *tq, *q, *ckv, *k, *v, *o, *x1, *h2, *qc, *kc, *vc, *oc, *x2, *h3, *gate, *up;
    cudaGetSymbolAddress((void**)&h,   g_h);
    cudaGetSymbolAddress((void**)&tq,  g_tq);
    cudaGetSymbolAddress((void**)&q,   g_q);
    cudaGetSymbolAddress((void**)&ckv, g_ckv);
    cudaGetSymbolAddress((void**)&k,   g_k);
    cudaGetSymbolAddress((void**)&v,   g_v);
    cudaGetSymbolAddress((void**)&o,   g_o);
    cudaGetSymbolAddress((void**)&x1,  g_x1);
    cudaGetSymbolAddress((void**)&h2,  g_h2);
    cudaGetSymbolAddress((void**)&qc,  g_qc);
    cudaGetSymbolAddress((void**)&kc,  g_kc);
    cudaGetSymbolAddress((void**)&vc,  g_vc);
    cudaGetSymbolAddress((void**)&oc,  g_oc);
    cudaGetSymbolAddress((void**)&x2,  g_x2);
    cudaGetSymbolAddress((void**)&h3,  g_h3);
    cudaGetSymbolAddress((void**)&gate,g_gate);
    cudaGetSymbolAddress((void**)&up,  g_up);

    int attn_smem = (4 * 64 * 65 + 3 * 64) * sizeof(float);
    cudaFuncSetAttribute(self_attn_kernel, cudaFuncAttributeMaxDynamicSharedMemorySize, attn_smem);

    // ---- Phase 1: MLA self-attention ----
    rmsnorm_kernel<<<NTOK, 256>>>(x, norm1_w, h, DD);
    sgemm_kernel<<<gemm_grid(NTOK, 32),  256>>>(h,   W_dq,  nullptr, tq,  NTOK, 32,  DD);
    sgemm_kernel<<<gemm_grid(NTOK, DD),  256>>>(tq,  W_uq,  nullptr, q,   NTOK, DD,  32);
    sgemm_kernel<<<gemm_grid(NTOK, 64),  256>>>(h,   W_dkv, nullptr, ckv, NTOK, 64,  DD);
    sgemm_kernel<<<gemm_grid(NTOK, DD),  256>>>(ckv, W_uk,  nullptr, k,   NTOK, DD,  64);
    sgemm_kernel<<<gemm_grid(NTOK, DD),  256>>>(ckv, W_uv,  nullptr, v,   NTOK, DD,  64);
    self_attn_kernel<<<dim3(SS / 64, HH, BB), 256, attn_smem>>>(q, k, v, o);
    sgemm_kernel<<<gemm_grid(NTOK, DD),  256>>>(o, W_o_self, x, x1, NTOK, DD, DD);

    // ---- Phase 2: windowed cross-attention ----
    rmsnorm_kernel<<<NTOK, 256>>>(x1, norm2_w, h2, DD);
    sgemm_kernel<<<gemm_grid(NTOK, DD), 256>>>(h2,     W_q_c, nullptr, qc, NTOK, DD, DD);
    sgemm_kernel<<<gemm_grid(MTOK, DD), 256>>>(memory, W_k_c, nullptr, kc, MTOK, DD, DD);
    sgemm_kernel<<<gemm_grid(MTOK, DD), 256>>>(memory, W_v_c, nullptr, vc, MTOK, DD, DD);
    cross_attn_kernel<<<dim3(NTOK, 4), 128>>>(qc, kc, vc, seg_ids, oc);
    sgemm_kernel<<<gemm_grid(NTOK, DD), 256>>>(oc, W_o_c, x1, x2, NTOK, DD, DD);

    // ---- Phase 3: SwiGLU MLP ----
    rmsnorm_kernel<<<NTOK, 256>>>(x2, norm3_w, h3, DD);
    sgemm_kernel<<<gemm_grid(NTOK, FF), 256>>>(h3, W_gate, nullptr, gate, NTOK, FF, DD);
    sgemm_kernel<<<gemm_grid(NTOK, FF), 256>>>(h3, W_up,   nullptr, up,   NTOK, FF, DD);
    silu_mul_kernel<<<(NTOK * FF + 255) / 256, 256>>>(gate, up, NTOK * FF);
    sgemm_kernel<<<gemm_grid(NTOK, DD), 256>>>(gate, W_down, x2, out, NTOK, DD, FF);
}

// round 3
// speedup vs baseline: 2.8025x; 2.8025x over previous
#include <cuda_runtime.h>
#include <cuda_bf16.h>
#include <math.h>
#include <stdint.h>

// Problem constants
#define BB   2
#define SS   2048
#define MM   512
#define DD   1024
#define HH   16
#define HD   64
#define NTOK (BB*SS)        // 4096
#define MTOK (BB*MM)        // 1024
#define FF   4096           // 4*D

// ---------------- scratch (device globals; no allocation) ----------------
__device__ float g_h   [NTOK*DD];
__device__ float g_tq  [NTOK*32];
__device__ float g_q   [NTOK*DD];
__device__ float g_ckv [NTOK*64];
__device__ float g_k   [NTOK*DD];
__device__ float g_v   [NTOK*DD];
__device__ float g_o   [NTOK*DD];
__device__ float g_x1  [NTOK*DD];
__device__ float g_h2  [NTOK*DD];
__device__ float g_qc  [NTOK*DD];
__device__ float g_kc  [MTOK*DD];
__device__ float g_vc  [MTOK*DD];
__device__ float g_oc  [NTOK*DD];
__device__ float g_x2  [NTOK*DD];
__device__ float g_h3  [NTOK*DD];
__device__ float g_gate[NTOK*FF];
__device__ float g_up  [NTOK*FF];

// tf32-rounded transposed weights: Wt[N][K] stored as float bits
__device__ float gw_dq    [DD*32];
__device__ float gw_uq    [32*DD];
__device__ float gw_dkv   [DD*64];
__device__ float gw_uk    [64*DD];
__device__ float gw_uv    [64*DD];
__device__ float gw_oself [DD*DD];
__device__ float gw_qc    [DD*DD];
__device__ float gw_kc    [DD*DD];
__device__ float gw_vc    [DD*DD];
__device__ float gw_oc    [DD*DD];
__device__ float gw_gate  [DD*FF];
__device__ float gw_up    [DD*FF];
__device__ float gw_down  [FF*DD];

__device__ __forceinline__ float f2tf32(float f) {
    uint32_t r;
    asm("cvt.rna.tf32.f32 %0, %1;" : "=r"(r) : "f"(f));
    return __uint_as_float(r);
}

// ---------------- weight convert+transpose: W fp32 [K][N] -> Wt tf32 [N][K] ----
__global__ void convert_w_kernel(const float* __restrict__ W, float* __restrict__ Wt,
                                 int K, int N) {
    __shared__ float t[32][33];
    int n0 = blockIdx.x * 32, k0 = blockIdx.y * 32;
    int tx = threadIdx.x, ty = threadIdx.y;   // 32 x 8
    #pragma unroll
    for (int i = 0; i < 4; i++) {
        int k = k0 + ty + i * 8;
        t[ty + i * 8][tx] = W[(size_t)k * N + n0 + tx];
    }
    __syncthreads();
    #pragma unroll
    for (int i = 0; i < 4; i++) {
        int n = n0 + ty + i * 8;
        Wt[(size_t)n * K + k0 + tx] = f2tf32(t[tx][ty + i * 8]);
    }
}

// ---------------- rmsnorm ----------------
__global__ void rmsnorm_kernel(const float* __restrict__ x, const float* __restrict__ w,
                               float* __restrict__ out, int D) {
    int row = blockIdx.x;
    const float* xr = x + (size_t)row * D;
    __shared__ float red[256];
    float s = 0.f;
    for (int i = threadIdx.x; i < D; i += 256) { float v = xr[i]; s += v * v; }
    red[threadIdx.x] = s; __syncthreads();
    for (int st = 128; st > 0; st >>= 1) {
        if (threadIdx.x < st) red[threadIdx.x] += red[threadIdx.x + st];
        __syncthreads();
    }
    float inv = rsqrtf(red[0] / (float)D + 1e-6f);
    for (int i = threadIdx.x; i < D; i += 256)
        out[(size_t)row * D + i] = xr[i] * inv * w[i];
}

// ---------------- tf32 MMA helper ----------------
__device__ __forceinline__ void mma1688(float* c, const uint32_t* a, const uint32_t* b) {
    asm volatile(
        "mma.sync.aligned.m16n8k8.row.col.f32.tf32.tf32.f32 "
        "{%0,%1,%2,%3}, {%4,%5,%6,%7}, {%8,%9}, {%0,%1,%2,%3};\n"
        : "+f"(c[0]), "+f"(c[1]), "+f"(c[2]), "+f"(c[3])
        : "r"(a[0]), "r"(a[1]), "r"(a[2]), "r"(a[3]), "r"(b[0]), "r"(b[1]));
}

// ---------------- tf32 tensor GEMM: C = A[MxK](f32) @ Wt^T (+R); Wt tf32 [N][K] ----
#define BMM 128
#define BNN 128
#define BKK 16
#define LDA 20   // smem row stride (floats), conflict-free for frag loads

__global__ __launch_bounds__(256)
void tgemm_kernel(const float* __restrict__ A, const float* __restrict__ Wt,
                  const float* __restrict__ R, float* __restrict__ C,
                  int M, int N, int K) {
    __shared__ float As[2][BMM * LDA];
    __shared__ float Bs[2][BNN * LDA];
    int tid = threadIdx.x;
    int lane = tid & 31, warp = tid >> 5;
    int wm = warp & 1, wn = warp >> 1;          // 2 x 4 warp grid (64 rows x 32 cols each)
    int bm = blockIdx.y * BMM, bn = blockIdx.x * BNN;

    float acc[4][4][4] = {};                    // [mt][nt][4]

    int ld_row = tid >> 1;                      // 0..127
    int ld_col = (tid & 1) * 8;                 // 0 or 8

    int iters = K / BKK;

    // prologue -> buf 0
    {
        const float* ap = &A[(size_t)(bm + ld_row) * K + ld_col];
        float4 f0 = *(const float4*)ap;
        float4 f1 = *(const float4*)(ap + 4);
        float4 r0 = make_float4(f2tf32(f0.x), f2tf32(f0.y), f2tf32(f0.z), f2tf32(f0.w));
        float4 r1 = make_float4(f2tf32(f1.x), f2tf32(f1.y), f2tf32(f1.z), f2tf32(f1.w));
        *(float4*)&As[0][ld_row * LDA + ld_col]     = r0;
        *(float4*)&As[0][ld_row * LDA + ld_col + 4] = r1;
        int n = bn + ld_row;
        float4 b0 = make_float4(0,0,0,0), b1 = make_float4(0,0,0,0);
        if (n < N) {
            const float* bp = &Wt[(size_t)n * K + ld_col];
            b0 = *(const float4*)bp;
            b1 = *(const float4*)(bp + 4);
        }
        *(float4*)&Bs[0][ld_row * LDA + ld_col]     = b0;
        *(float4*)&Bs[0][ld_row * LDA + ld_col + 4] = b1;
    }
    __syncthreads();

    for (int it = 0; it < iters; it++) {
        int cur = it & 1, nxt = cur ^ 1;
        float4 Ar0, Ar1, Br0, Br1;
        bool pf = (it + 1 < iters);
        if (pf) {
            int k0 = (it + 1) * BKK;
            const float* ap = &A[(size_t)(bm + ld_row) * K + k0 + ld_col];
            Ar0 = *(const float4*)ap;
            Ar1 = *(const float4*)(ap + 4);
            int n = bn + ld_row;
            Br0 = make_float4(0,0,0,0); Br1 = make_float4(0,0,0,0);
            if (n < N) {
                const float* bp = &Wt[(size_t)n * K + k0 + ld_col];
                Br0 = *(const float4*)bp;
                Br1 = *(const float4*)(bp + 4);
            }
        }
        // compute
        #pragma unroll
        for (int ks = 0; ks < 2; ks++) {
            int kb = ks * 8 + (lane & 3);
            uint32_t afr[4][4], bfr[4][2];
            #pragma unroll
            for (int mt = 0; mt < 4; mt++) {
                int r0 = wm * 64 + mt * 16 + (lane >> 2);
                afr[mt][0] = __float_as_uint(As[cur][r0 * LDA + kb]);
                afr[mt][1] = __float_as_uint(As[cur][(r0 + 8) * LDA + kb]);
                afr[mt][2] = __float_as_uint(As[cur][r0 * LDA + kb + 4]);
                afr[mt][3] = __float_as_uint(As[cur][(r0 + 8) * LDA + kb + 4]);
            }
            #pragma unroll
            for (int nt = 0; nt < 4; nt++) {
                int n0 = wn * 32 + nt * 8 + (lane >> 2);
                bfr[nt][0] = __float_as_uint(Bs[cur][n0 * LDA + kb]);
                bfr[nt][1] = __float_as_uint(Bs[cur][n0 * LDA + kb + 4]);
            }
            #pragma unroll
            for (int mt = 0; mt < 4; mt++)
                #pragma unroll
                for (int nt = 0; nt < 4; nt++)
                    mma1688(acc[mt][nt], afr[mt], bfr[nt]);
        }
        if (pf) {
            float4 r0 = make_float4(f2tf32(Ar0.x), f2tf32(Ar0.y), f2tf32(Ar0.z), f2tf32(Ar0.w));
            float4 r1 = make_float4(f2tf32(Ar1.x), f2tf32(Ar1.y), f2tf32(Ar1.z), f2tf32(Ar1.w));
            *(float4*)&As[nxt][ld_row * LDA + ld_col]     = r0;
            *(float4*)&As[nxt][ld_row * LDA + ld_col + 4] = r1;
            *(float4*)&Bs[nxt][ld_row * LDA + ld_col]     = Br0;
            *(float4*)&Bs[nxt][ld_row * LDA + ld_col + 4] = Br1;
        }
        __syncthreads();
    }

    // epilogue
    #pragma unroll
    for (int mt = 0; mt < 4; mt++) {
        int r0 = bm + wm * 64 + mt * 16 + (lane >> 2);
        #pragma unroll
        for (int nt = 0; nt < 4; nt++) {
            int cn = bn + wn * 32 + nt * 8 + (lane & 3) * 2;
            if (cn < N) {
                float2 v0 = make_float2(acc[mt][nt][0], acc[mt][nt][1]);
                float2 v1 = make_float2(acc[mt][nt][2], acc[mt][nt][3]);
                if (R) {
                    float2 ra = *(const float2*)&R[(size_t)r0 * N + cn];
                    float2 rb = *(const float2*)&R[(size_t)(r0 + 8) * N + cn];
                    v0.x += ra.x; v0.y += ra.y;
                    v1.x += rb.x; v1.y += rb.y;
                }
                *(float2*)&C[(size_t)r0 * N + cn] = v0;
                *(float2*)&C[(size_t)(r0 + 8) * N + cn] = v1;
            }
        }
    }
}

// ---------------- self attention: flash-style, tf32 tensor cores ----------------
// grid (S/64, H, B), 256 threads (8 warps: wm=warp%4 -> 16 rows, wn=warp/4 -> 32 cols)
#define ATT_LD 68
__global__ __launch_bounds__(256)
void self_attn_kernel(const float* __restrict__ q, const float* __restrict__ k,
                      const float* __restrict__ v, float* __restrict__ o) {
    extern __shared__ float sm[];
    float* Qs = sm;                    // [64][68]
    float* Ks = Qs + 64 * ATT_LD;      // [64][68]  (row j, col d) = B operand n-major
    float* Vt = Ks + 64 * ATT_LD;      // [64][68]  transposed: Vt[d][j]
    float* Ps = Vt + 64 * ATT_LD;      // [64][68]
    float* row_max  = Ps + 64 * ATT_LD;
    float* row_sum  = row_max + 64;
    float* row_corr = row_sum + 64;

    int qt = blockIdx.x, h = blockIdx.y, b = blockIdx.z;
    int q0 = qt * 64;
    int tid = threadIdx.x;
    int lane = tid & 31, warp = tid >> 5;
    int wm = warp & 3, wn = warp >> 2;      // 4 x 2

    // load Q (scaled, tf32-rounded)
    for (int idx = tid; idx < 64 * 64; idx += 256) {
        int r = idx >> 6, c = idx & 63;
        Qs[r * ATT_LD + c] = f2tf32(q[((size_t)(b * SS + q0 + r)) * DD + h * HD + c] * 0.125f);
    }
    if (tid < 64) { row_max[tid] = -INFINITY; row_sum[tid] = 0.f; }
    float acc[4][4] = {};                   // O tile frags: [nt][4]
    __syncthreads();

    for (int jt = 0; jt <= qt; jt++) {
        int kv0 = jt * 64;
        for (int idx = tid; idx < 64 * 64; idx += 256) {
            int r = idx >> 6, c = idx & 63;
            size_t base = ((size_t)(b * SS + kv0 + r)) * DD + h * HD + c;
            Ks[r * ATT_LD + c] = f2tf32(k[base]);
            Vt[c * ATT_LD + r] = f2tf32(v[base]);
        }
        __syncthreads();

        // S = Q @ K^T  (A = Qs row-major, B = Ks n-major)
        float sacc[4][4] = {};
        #pragma unroll
        for (int ks = 0; ks < 8; ks++) {
            int kb = ks * 8 + (lane & 3);
            uint32_t afr[4], bfr[4][2];
            int r0 = wm * 16 + (lane >> 2);
            afr[0] = __float_as_uint(Qs[r0 * ATT_LD + kb]);
            afr[1] = __float_as_uint(Qs[(r0 + 8) * ATT_LD + kb]);
            afr[2] = __float_as_uint(Qs[r0 * ATT_LD + kb + 4]);
            afr[3] = __float_as_uint(Qs[(r0 + 8) * ATT_LD + kb + 4]);
            #pragma unroll
            for (int nt = 0; nt < 4; nt++) {
                int n0 = wn * 32 + nt * 8 + (lane >> 2);
                bfr[nt][0] = __float_as_uint(Ks[n0 * ATT_LD + kb]);
                bfr[nt][1] = __float_as_uint(Ks[n0 * ATT_LD + kb + 4]);
            }
            #pragma unroll
            for (int nt = 0; nt < 4; nt++)
                mma1688(sacc[nt], afr, bfr[nt]);
        }
        // mask + store S to Ps
        bool diag = (jt == qt);
        #pragma unroll
        for (int nt = 0; nt < 4; nt++) {
            int lr0 = wm * 16 + (lane >> 2);
            int lc0 = wn * 32 + nt * 8 + (lane & 3) * 2;
            #pragma unroll
            for (int e = 0; e < 4; e++) {
                int lr = lr0 + (e >> 1) * 8;
                int lc = lc0 + (e & 1);
                float sv = sacc[nt][e];
                if (diag && (kv0 + lc > q0 + lr)) sv = -INFINITY;
                Ps[lr * ATT_LD + lc] = sv;
            }
        }
        __syncthreads();

        // online softmax (64 rows, one thread each)
        if (tid < 64) {
            float m = row_max[tid];
            float tm = -INFINITY;
            for (int c = 0; c < 64; c++) tm = fmaxf(tm, Ps[tid * ATT_LD + c]);
            float nm = fmaxf(m, tm);
            float corr = __expf(m - nm);
            float s = 0.f;
            for (int c = 0; c < 64; c++) {
                float p = f2tf32(__expf(Ps[tid * ATT_LD + c] - nm));
                Ps[tid * ATT_LD + c] = p;
                s += p;
            }
            row_sum[tid]  = row_sum[tid] * corr + s;
            row_max[tid]  = nm;
            row_corr[tid] = corr;
        }
        __syncthreads();

        // rescale acc by corr, then acc += P @ V   (A = Ps, B = Vt n-major over d)
        {
            int r0 = wm * 16 + (lane >> 2);
            float c0 = row_corr[r0], c1 = row_corr[r0 + 8];
            #pragma unroll
            for (int nt = 0; nt < 4; nt++) {
                acc[nt][0] *= c0; acc[nt][1] *= c0;
                acc[nt][2] *= c1; acc[nt][3] *= c1;
            }
        }
        #pragma unroll
        for (int ks = 0; ks < 8; ks++) {
            int kb = ks * 8 + (lane & 3);               // j index
            uint32_t afr[4], bfr[4][2];
            int r0 = wm * 16 + (lane >> 2);
            afr[0] = __float_as_uint(Ps[r0 * ATT_LD + kb]);
            afr[1] = __float_as_uint(Ps[(r0 + 8) * ATT_LD + kb]);
            afr[2] = __float_as_uint(Ps[r0 * ATT_LD + kb + 4]);
            afr[3] = __float_as_uint(Ps[(r0 + 8) * ATT_LD + kb + 4]);
            #pragma unroll
            for (int nt = 0; nt < 4; nt++) {
                int d0 = wn * 32 + nt * 8 + (lane >> 2);
                bfr[nt][0] = __float_as_uint(Vt[d0 * ATT_LD + kb]);
                bfr[nt][1] = __float_as_uint(Vt[d0 * ATT_LD + kb + 4]);
            }
            #pragma unroll
            for (int nt = 0; nt < 4; nt++)
                mma1688(acc[nt], afr, bfr[nt]);
        }
        __syncthreads();
    }

    // write O
    {
        int r0 = wm * 16 + (lane >> 2);
        float i0 = 1.f / row_sum[r0], i1 = 1.f / row_sum[r0 + 8];
        #pragma unroll
        for (int nt = 0; nt < 4; nt++) {
            int c0 = wn * 32 + nt * 8 + (lane & 3) * 2;
            size_t ra = ((size_t)(b * SS + q0 + r0)) * DD + h * HD + c0;
            size_t rb = ((size_t)(b * SS + q0 + r0 + 8)) * DD + h * HD + c0;
            *(float2*)&o[ra] = make_float2(acc[nt][0] * i0, acc[nt][1] * i0);
            *(float2*)&o[rb] = make_float2(acc[nt][2] * i1, acc[nt][3] * i1);
        }
    }
}

// ---------------- cross attention (windowed, <=9 keys) ----------------
__global__ void cross_attn_kernel(const float* __restrict__ qc, const float* __restrict__ kc,
                                  const float* __restrict__ vc, const int* __restrict__ seg_ids,
                                  float* __restrict__ oc) {
    int n = blockIdx.x;
    int warp = threadIdx.x / 32;
    int lane = threadIdx.x % 32;
    int h = blockIdx.y * 4 + warp;
    int b = n / SS;
    int seg = seg_ids[n];
    int jlo = seg - 8; if (jlo < 0) jlo = 0;
    int cnt = seg - jlo + 1;

    const float* qv = qc + (size_t)n * DD + h * HD;
    float q0v = qv[lane], q1v = qv[lane + 32];

    float sc[9];
    float mx = -INFINITY;
    for (int t = 0; t < cnt; t++) {
        const float* kv = kc + ((size_t)(b * MM + jlo + t)) * DD + h * HD;
        float p = q0v * kv[lane] + q1v * kv[lane + 32];
        #pragma unroll
        for (int off = 16; off > 0; off >>= 1)
            p += __shfl_xor_sync(0xffffffff, p, off);
        p *= 0.125f;
        sc[t] = p;
        mx = fmaxf(mx, p);
    }
    float sum = 0.f;
    for (int t = 0; t < cnt; t++) { sc[t] = __expf(sc[t] - mx); sum += sc[t]; }
    float o0 = 0.f, o1 = 0.f;
    for (int t = 0; t < cnt; t++) {
        const float* vv = vc + ((size_t)(b * MM + jlo + t)) * DD + h * HD;
        o0 += sc[t] * vv[lane];
        o1 += sc[t] * vv[lane + 32];
    }
    float inv = 1.f / sum;
    oc[(size_t)n * DD + h * HD + lane]      = o0 * inv;
    oc[(size_t)n * DD + h * HD + lane + 32] = o1 * inv;
}

// ---------------- silu(g)*u ----------------
__global__ void silu_mul_kernel(float* __restrict__ g, const float* __restrict__ u, int n) {
    int i = blockIdx.x * blockDim.x + threadIdx.x;
    if (i < n) {
        float gv = g[i];
        float s = gv / (1.f + __expf(-gv));
        g[i] = s * u[i];
    }
}

// ---------------- launch ----------------
static inline dim3 tg_grid(int M, int N) { return dim3((N + BNN - 1) / BNN, M / BMM); }
static inline dim3 cw_grid(int K, int N) { return dim3(N / 32, K / 32); }

extern "C" void kernel_launch(void* const* d_in, const int* in_sizes, int n_in,
                              void* d_out, int out_size) {
    const float* x        = (const float*)d_in[0];
    const float* memory   = (const float*)d_in[1];
    const int*   seg_ids  = (const int*)  d_in[2];
    const float* norm1_w  = (const float*)d_in[3];
    const float* W_dq     = (const float*)d_in[4];
    const float* W_uq     = (const float*)d_in[5];
    const float* W_dkv    = (const float*)d_in[6];
    const float* W_uk     = (const float*)d_in[7];
    const float* W_uv     = (const float*)d_in[8];
    const float* W_o_self = (const float*)d_in[9];
    const float* norm2_w  = (const float*)d_in[10];
    const float* W_q_c    = (const float*)d_in[11];
    const float* W_k_c    = (const float*)d_in[12];
    const float* W_v_c    = (const float*)d_in[13];
    const float* W_o_c    = (const float*)d_in[14];
    const float* norm3_w  = (const float*)d_in[15];
    const float* W_gate   = (const float*)d_in[16];
    const float* W_up     = (const float*)d_in[17];
    const float* W_down   = (const float*)d_in[18];
    float* out = (float*)d_out;

    float *h, *tq, *q, *ckv, *k, *v, *o, *x1, *h2, *qc, *kc, *vc, *oc, *x2, *h3, *gate, *up;
    cudaGetSymbolAddress((void**)&h,   g_h);
    cudaGetSymbolAddress((void**)&tq,  g_tq);
    cudaGetSymbolAddress((void**)&q,   g_q);
    cudaGetSymbolAddress((void**)&ckv, g_ckv);
    cudaGetSymbolAddress((void**)&k,   g_k);
    cudaGetSymbolAddress((void**)&v,   g_v);
    cudaGetSymbolAddress((void**)&o,   g_o);
    cudaGetSymbolAddress((void**)&x1,  g_x1);
    cudaGetSymbolAddress((void**)&h2,  g_h2);
    cudaGetSymbolAddress((void**)&qc,  g_qc);
    cudaGetSymbolAddress((void**)&kc,  g_kc);
    cudaGetSymbolAddress((void**)&vc,  g_vc);
    cudaGetSymbolAddress((void**)&oc,  g_oc);
    cudaGetSymbolAddress((void**)&x2,  g_x2);
    cudaGetSymbolAddress((void**)&h3,  g_h3);
    cudaGetSymbolAddress((void**)&gate,g_gate);
    cudaGetSymbolAddress((void**)&up,  g_up);

    float *w_dq, *w_uq, *w_dkv, *w_uk, *w_uv, *w_oself, *w_qc, *w_kc, *w_vc, *w_oc,
          *w_gate, *w_up, *w_down;
    cudaGetSymbolAddress((void**)&w_dq,    gw_dq);
    cudaGetSymbolAddress((void**)&w_uq,    gw_uq);
    cudaGetSymbolAddress((void**)&w_dkv,   gw_dkv);
    cudaGetSymbolAddress((void**)&w_uk,    gw_uk);
    cudaGetSymbolAddress((void**)&w_uv,    gw_uv);
    cudaGetSymbolAddress((void**)&w_oself, gw_oself);
    cudaGetSymbolAddress((void**)&w_qc,    gw_qc);
    cudaGetSymbolAddress((void**)&w_kc,    gw_kc);
    cudaGetSymbolAddress((void**)&w_vc,    gw_vc);
    cudaGetSymbolAddress((void**)&w_oc,    gw_oc);
    cudaGetSymbolAddress((void**)&w_gate,  gw_gate);
    cudaGetSymbolAddress((void**)&w_up,    gw_up);
    cudaGetSymbolAddress((void**)&w_down,  gw_down);

    dim3 cb(32, 8);
    convert_w_kernel<<<cw_grid(DD, 32),  cb>>>(W_dq,     w_dq,    DD, 32);
    convert_w_kernel<<<cw_grid(32, DD),  cb>>>(W_uq,     w_uq,    32, DD);
    convert_w_kernel<<<cw_grid(DD, 64),  cb>>>(W_dkv,    w_dkv,   DD, 64);
    convert_w_kernel<<<cw_grid(64, DD),  cb>>>(W_uk,     w_uk,    64, DD);
    convert_w_kernel<<<cw_grid(64, DD),  cb>>>(W_uv,     w_uv,    64, DD);
    convert_w_kernel<<<cw_grid(DD, DD),  cb>>>(W_o_self, w_oself, DD, DD);
    convert_w_kernel<<<cw_grid(DD, DD),  cb>>>(W_q_c,    w_qc,    DD, DD);
    convert_w_kernel<<<cw_grid(DD, DD),  cb>>>(W_k_c,    w_kc,    DD, DD);
    convert_w_kernel<<<cw_grid(DD, DD),  cb>>>(W_v_c,    w_vc,    DD, DD);
    convert_w_kernel<<<cw_grid(DD, DD),  cb>>>(W_o_c,    w_oc,    DD, DD);
    convert_w_kernel<<<cw_grid(DD, FF),  cb>>>(W_gate,   w_gate,  DD, FF);
    convert_w_kernel<<<cw_grid(DD, FF),  cb>>>(W_up,     w_up,    DD, FF);
    convert_w_kernel<<<cw_grid(FF, DD),  cb>>>(W_down,   w_down,  FF, DD);

    int attn_smem = (4 * 64 * ATT_LD + 3 * 64) * sizeof(float);
    cudaFuncSetAttribute(self_attn_kernel, cudaFuncAttributeMaxDynamicSharedMemorySize, attn_smem);

    // ---- Phase 1: MLA self-attention ----
    rmsnorm_kernel<<<NTOK, 256>>>(x, norm1_w, h, DD);
    tgemm_kernel<<<tg_grid(NTOK, 32),  256>>>(h,   w_dq,  nullptr, tq,  NTOK, 32,  DD);
    tgemm_kernel<<<tg_grid(NTOK, DD),  256>>>(tq,  w_uq,  nullptr, q,   NTOK, DD,  32);
    tgemm_kernel<<<tg_grid(NTOK, 64),  256>>>(h,   w_dkv, nullptr, ckv, NTOK, 64,  DD);
    tgemm_kernel<<<tg_grid(NTOK, DD),  256>>>(ckv, w_uk,  nullptr, k,   NTOK, DD,  64);
    tgemm_kernel<<<tg_grid(NTOK, DD),  256>>>(ckv, w_uv,  nullptr, v,   NTOK, DD,  64);
    self_attn_kernel<<<dim3(SS / 64, HH, BB), 256, attn_smem>>>(q, k, v, o);
    tgemm_kernel<<<tg_grid(NTOK, DD),  256>>>(o, w_oself, x, x1, NTOK, DD, DD);

    // ---- Phase 2: windowed cross-attention ----
    rmsnorm_kernel<<<NTOK, 256>>>(x1, norm2_w, h2, DD);
    tgemm_kernel<<<tg_grid(NTOK, DD), 256>>>(h2,     w_qc, nullptr, qc, NTOK, DD, DD);
    tgemm_kernel<<<tg_grid(MTOK, DD), 256>>>(memory, w_kc, nullptr, kc, MTOK, DD, DD);
    tgemm_kernel<<<tg_grid(MTOK, DD), 256>>>(memory, w_vc, nullptr, vc, MTOK, DD, DD);
    cross_attn_kernel<<<dim3(NTOK, 4), 128>>>(qc, kc, vc, seg_ids, oc);
    tgemm_kernel<<<tg_grid(NTOK, DD), 256>>>(oc, w_oc, x1, x2, NTOK, DD, DD);

    // ---- Phase 3: SwiGLU MLP ----
    rmsnorm_kernel<<<NTOK, 256>>>(x2, norm3_w, h3, DD);
    tgemm_kernel<<<tg_grid(NTOK, FF), 256>>>(h3, w_gate, nullptr, gate, NTOK, FF, DD);
    tgemm_kernel<<<tg_grid(NTOK, FF), 256>>>(h3, w_up,   nullptr, up,   NTOK, FF, DD);
    silu_mul_kernel<<<(NTOK * FF + 255) / 256, 256>>>(gate, up, NTOK * FF);
    tgemm_kernel<<<tg_grid(NTOK, DD), 256>>>(gate, w_down, x2, out, NTOK, DD, FF);
}

// round 4
// speedup vs baseline: 3.1749x; 1.1329x over previous
#include <cuda_runtime.h>
#include <cuda_bf16.h>
#include <math.h>
#include <stdint.h>

// Problem constants
#define BB   2
#define SS   2048
#define MM   512
#define DD   1024
#define HH   16
#define HD   64
#define NTOK (BB*SS)        // 4096
#define MTOK (BB*MM)        // 1024
#define FF   4096           // 4*D

// ---------------- scratch (device globals; no allocation) ----------------
__device__ float g_h   [NTOK*DD];
__device__ float g_tq  [NTOK*32];
__device__ float g_q   [NTOK*DD];
__device__ float g_ckv [NTOK*64];
__device__ float g_k   [NTOK*DD];
__device__ float g_v   [NTOK*DD];
__device__ float g_o   [NTOK*DD];
__device__ float g_x1  [NTOK*DD];
__device__ float g_h2  [NTOK*DD];
__device__ float g_qc  [NTOK*DD];
__device__ float g_kc  [MTOK*DD];
__device__ float g_vc  [MTOK*DD];
__device__ float g_oc  [NTOK*DD];
__device__ float g_x2  [NTOK*DD];
__device__ float g_h3  [NTOK*DD];
__device__ float g_gate[NTOK*FF];
__device__ float g_up  [NTOK*FF];
__device__ float g_mem [MTOK*DD];   // tf32-rounded copy of memory

// tf32-rounded transposed weights: Wt[N][K] stored as float bits
__device__ float gw_dq    [DD*32];
__device__ float gw_uq    [32*DD];
__device__ float gw_dkv   [DD*64];
__device__ float gw_uk    [64*DD];
__device__ float gw_uv    [64*DD];
__device__ float gw_oself [DD*DD];
__device__ float gw_qc    [DD*DD];
__device__ float gw_kc    [DD*DD];
__device__ float gw_vc    [DD*DD];
__device__ float gw_oc    [DD*DD];
__device__ float gw_gate  [DD*FF];
__device__ float gw_up    [DD*FF];
__device__ float gw_down  [FF*DD];

__device__ __forceinline__ float f2tf32(float f) {
    uint32_t r;
    asm("cvt.rna.tf32.f32 %0, %1;" : "=r"(r) : "f"(f));
    return __uint_as_float(r);
}

// ---------------- fused weight convert+transpose ----------------
struct WDesc { const float* src; float* dst; int K; int N; int tile0; };
struct WTable { WDesc w[13]; };

__global__ void convert_all_kernel(WTable t) {
    __shared__ float tl[32][33];
    int bid = blockIdx.x;
    int wi = 0;
    #pragma unroll
    for (int i = 1; i < 13; i++) if (bid >= t.w[i].tile0) wi = i;
    const WDesc d = t.w[wi];
    int lt = bid - d.tile0;
    int ntiles_n = d.N >> 5;
    int n0 = (lt % ntiles_n) * 32;
    int k0 = (lt / ntiles_n) * 32;
    int tx = threadIdx.x & 31, ty = threadIdx.x >> 5;   // 32 x 8
    #pragma unroll
    for (int i = 0; i < 4; i++) {
        int k = k0 + ty + i * 8;
        tl[ty + i * 8][tx] = d.src[(size_t)k * d.N + n0 + tx];
    }
    __syncthreads();
    #pragma unroll
    for (int i = 0; i < 4; i++) {
        int n = n0 + ty + i * 8;
        d.dst[(size_t)n * d.K + k0 + tx] = f2tf32(tl[tx][ty + i * 8]);
    }
}

// ---------------- round-copy (memory -> tf32) ----------------
__global__ void round_copy_kernel(const float* __restrict__ in, float* __restrict__ out, int n) {
    int i = blockIdx.x * blockDim.x + threadIdx.x;
    if (i < n) out[i] = f2tf32(in[i]);
}

// ---------------- rmsnorm (tf32-rounded output) ----------------
__global__ void rmsnorm_kernel(const float* __restrict__ x, const float* __restrict__ w,
                               float* __restrict__ out, int D) {
    int row = blockIdx.x;
    const float* xr = x + (size_t)row * D;
    __shared__ float red[256];
    float s = 0.f;
    for (int i = threadIdx.x; i < D; i += 256) { float v = xr[i]; s += v * v; }
    red[threadIdx.x] = s; __syncthreads();
    for (int st = 128; st > 0; st >>= 1) {
        if (threadIdx.x < st) red[threadIdx.x] += red[threadIdx.x + st];
        __syncthreads();
    }
    float inv = rsqrtf(red[0] / (float)D + 1e-6f);
    for (int i = threadIdx.x; i < D; i += 256)
        out[(size_t)row * D + i] = f2tf32(xr[i] * inv * w[i]);
}

// ---------------- tf32 MMA helper ----------------
__device__ __forceinline__ void mma1688(float* c, const uint32_t* a, const uint32_t* b) {
    asm volatile(
        "mma.sync.aligned.m16n8k8.row.col.f32.tf32.tf32.f32 "
        "{%0,%1,%2,%3}, {%4,%5,%6,%7}, {%8,%9}, {%0,%1,%2,%3};\n"
        : "+f"(c[0]), "+f"(c[1]), "+f"(c[2]), "+f"(c[3])
        : "r"(a[0]), "r"(a[1]), "r"(a[2]), "r"(a[3]), "r"(b[0]), "r"(b[1]));
}

__device__ __forceinline__ void cpasync16(float* dst, const float* src, int sz) {
    uint32_t d = (uint32_t)__cvta_generic_to_shared(dst);
    asm volatile("cp.async.cg.shared.global [%0], [%1], 16, %2;\n"
                 :: "r"(d), "l"(src), "r"(sz));
}

// ---------------- tf32 tensor GEMM, cp.async 3-stage ----------------
// C = A[MxK] @ Wt^T (+R); Wt tf32 [N][K]; A pre-rounded tf32
#define BMM 128
#define BNN 128
#define BKK 16
#define LDA 20
#define STG 3
#define STAGE_F (128 * LDA)   // floats per tensor per stage

__global__ __launch_bounds__(256)
void tgemm_kernel(const float* __restrict__ A, const float* __restrict__ Wt,
                  const float* __restrict__ R, float* __restrict__ C,
                  int M, int N, int K, int roundOut) {
    extern __shared__ float dsm[];
    float* As = dsm;                    // [STG][STAGE_F]
    float* Bs = dsm + STG * STAGE_F;    // [STG][STAGE_F]

    int tid = threadIdx.x;
    int lane = tid & 31, warp = tid >> 5;
    int wm = warp & 1, wn = warp >> 1;          // 2 x 4 warps (64 rows x 32 cols each)
    int bm = blockIdx.y * BMM, bn = blockIdx.x * BNN;

    float acc[4][4][4] = {};

    int ld_row = tid >> 1;                      // 0..127
    int ld_col = (tid & 1) * 8;                 // 0 or 8

    int iters = K / BKK;

    const float* aRow = A + (size_t)(bm + ld_row) * K + ld_col;
    int nIdx = bn + ld_row;
    int bsz = (nIdx < N) ? 16 : 0;
    const float* bRow = Wt + (size_t)(nIdx < N ? nIdx : N - 1) * K + ld_col;
    float* aDstBase = As + ld_row * LDA + ld_col;
    float* bDstBase = Bs + ld_row * LDA + ld_col;

    // prologue: stages 0 and 1
    #pragma unroll
    for (int s = 0; s < 2; s++) {
        int k0 = s * BKK;
        cpasync16(aDstBase + s * STAGE_F,     aRow + k0,     16);
        cpasync16(aDstBase + s * STAGE_F + 4, aRow + k0 + 4, 16);
        cpasync16(bDstBase + s * STAGE_F,     bRow + k0,     bsz);
        cpasync16(bDstBase + s * STAGE_F + 4, bRow + k0 + 4, bsz);
        asm volatile("cp.async.commit_group;\n" ::: "memory");
    }

    for (int it = 0; it < iters; it++) {
        if (it + 1 < iters) asm volatile("cp.async.wait_group 1;\n" ::: "memory");
        else                asm volatile("cp.async.wait_group 0;\n" ::: "memory");
        __syncthreads();

        int pre = it + 2;
        if (pre < iters) {
            int s = pre % STG;
            int k0 = pre * BKK;
            cpasync16(aDstBase + s * STAGE_F,     aRow + k0,     16);
            cpasync16(aDstBase + s * STAGE_F + 4, aRow + k0 + 4, 16);
            cpasync16(bDstBase + s * STAGE_F,     bRow + k0,     bsz);
            cpasync16(bDstBase + s * STAGE_F + 4, bRow + k0 + 4, bsz);
            asm volatile("cp.async.commit_group;\n" ::: "memory");
        }

        const float* Ac = As + (it % STG) * STAGE_F;
        const float* Bc = Bs + (it % STG) * STAGE_F;
        #pragma unroll
        for (int ks = 0; ks < 2; ks++) {
            int kb = ks * 8 + (lane & 3);
            uint32_t afr[4][4], bfr[4][2];
            #pragma unroll
            for (int mt = 0; mt < 4; mt++) {
                int r0 = wm * 64 + mt * 16 + (lane >> 2);
                afr[mt][0] = __float_as_uint(Ac[r0 * LDA + kb]);
                afr[mt][1] = __float_as_uint(Ac[(r0 + 8) * LDA + kb]);
                afr[mt][2] = __float_as_uint(Ac[r0 * LDA + kb + 4]);
                afr[mt][3] = __float_as_uint(Ac[(r0 + 8) * LDA + kb + 4]);
            }
            #pragma unroll
            for (int nt = 0; nt < 4; nt++) {
                int n0 = wn * 32 + nt * 8 + (lane >> 2);
                bfr[nt][0] = __float_as_uint(Bc[n0 * LDA + kb]);
                bfr[nt][1] = __float_as_uint(Bc[n0 * LDA + kb + 4]);
            }
            #pragma unroll
            for (int mt = 0; mt < 4; mt++)
                #pragma unroll
                for (int nt = 0; nt < 4; nt++)
                    mma1688(acc[mt][nt], afr[mt], bfr[nt]);
        }
    }

    // epilogue
    #pragma unroll
    for (int mt = 0; mt < 4; mt++) {
        int r0 = bm + wm * 64 + mt * 16 + (lane >> 2);
        #pragma unroll
        for (int nt = 0; nt < 4; nt++) {
            int cn = bn + wn * 32 + nt * 8 + (lane & 3) * 2;
            if (cn < N) {
                float2 v0 = make_float2(acc[mt][nt][0], acc[mt][nt][1]);
                float2 v1 = make_float2(acc[mt][nt][2], acc[mt][nt][3]);
                if (R) {
                    float2 ra = *(const float2*)&R[(size_t)r0 * N + cn];
                    float2 rb = *(const float2*)&R[(size_t)(r0 + 8) * N + cn];
                    v0.x += ra.x; v0.y += ra.y;
                    v1.x += rb.x; v1.y += rb.y;
                }
                if (roundOut) {
                    v0.x = f2tf32(v0.x); v0.y = f2tf32(v0.y);
                    v1.x = f2tf32(v1.x); v1.y = f2tf32(v1.y);
                }
                *(float2*)&C[(size_t)r0 * N + cn] = v0;
                *(float2*)&C[(size_t)(r0 + 8) * N + cn] = v1;
            }
        }
    }
}

// ---------------- self attention: flash-style, tf32 MMA, parallel softmax ----------------
#define ATT_LD 68
__global__ __launch_bounds__(256)
void self_attn_kernel(const float* __restrict__ q, const float* __restrict__ k,
                      const float* __restrict__ v, float* __restrict__ o) {
    extern __shared__ float sm[];
    float* Qs = sm;                    // [64][68]
    float* Ks = Qs + 64 * ATT_LD;
    float* Vt = Ks + 64 * ATT_LD;      // transposed: Vt[d][j]
    float* Ps = Vt + 64 * ATT_LD;
    float* row_max  = Ps + 64 * ATT_LD;
    float* row_sum  = row_max + 64;
    float* row_corr = row_sum + 64;

    int qt = blockIdx.x, h = blockIdx.y, b = blockIdx.z;
    int q0 = qt * 64;
    int tid = threadIdx.x;
    int lane = tid & 31, warp = tid >> 5;
    int wm = warp & 3, wn = warp >> 2;      // 4 x 2

    int srow = tid >> 2;                    // softmax: 4 threads per row
    int sseg = tid & 3;

    for (int idx = tid; idx < 64 * 64; idx += 256) {
        int r = idx >> 6, c = idx & 63;
        Qs[r * ATT_LD + c] = q[((size_t)(b * SS + q0 + r)) * DD + h * HD + c] * 0.125f;
    }
    if (tid < 64) { row_max[tid] = -INFINITY; row_sum[tid] = 0.f; }
    float acc[4][4] = {};
    __syncthreads();

    for (int jt = 0; jt <= qt; jt++) {
        int kv0 = jt * 64;
        for (int idx = tid; idx < 64 * 64; idx += 256) {
            int r = idx >> 6, c = idx & 63;
            size_t base = ((size_t)(b * SS + kv0 + r)) * DD + h * HD + c;
            Ks[r * ATT_LD + c] = k[base];
            Vt[c * ATT_LD + r] = v[base];
        }
        __syncthreads();

        // S = Q @ K^T
        float sacc[4][4] = {};
        #pragma unroll
        for (int ks = 0; ks < 8; ks++) {
            int kb = ks * 8 + (lane & 3);
            uint32_t afr[4], bfr[4][2];
            int r0 = wm * 16 + (lane >> 2);
            afr[0] = __float_as_uint(Qs[r0 * ATT_LD + kb]);
            afr[1] = __float_as_uint(Qs[(r0 + 8) * ATT_LD + kb]);
            afr[2] = __float_as_uint(Qs[r0 * ATT_LD + kb + 4]);
            afr[3] = __float_as_uint(Qs[(r0 + 8) * ATT_LD + kb + 4]);
            #pragma unroll
            for (int nt = 0; nt < 4; nt++) {
                int n0 = wn * 32 + nt * 8 + (lane >> 2);
                bfr[nt][0] = __float_as_uint(Ks[n0 * ATT_LD + kb]);
                bfr[nt][1] = __float_as_uint(Ks[n0 * ATT_LD + kb + 4]);
            }
            #pragma unroll
            for (int nt = 0; nt < 4; nt++)
                mma1688(sacc[nt], afr, bfr[nt]);
        }
        bool diag = (jt == qt);
        #pragma unroll
        for (int nt = 0; nt < 4; nt++) {
            int lr0 = wm * 16 + (lane >> 2);
            int lc0 = wn * 32 + nt * 8 + (lane & 3) * 2;
            #pragma unroll
            for (int e = 0; e < 4; e++) {
                int lr = lr0 + (e >> 1) * 8;
                int lc = lc0 + (e & 1);
                float sv = sacc[nt][e];
                if (diag && (kv0 + lc > q0 + lr)) sv = -INFINITY;
                Ps[lr * ATT_LD + lc] = sv;
            }
        }
        __syncthreads();

        // online softmax: 4 threads/row, 16 cols each
        {
            float* pr = Ps + srow * ATT_LD + sseg * 16;
            float m0 = row_max[srow];
            float tm = -INFINITY;
            #pragma unroll
            for (int c = 0; c < 16; c++) tm = fmaxf(tm, pr[c]);
            tm = fmaxf(tm, __shfl_xor_sync(0xffffffff, tm, 1));
            tm = fmaxf(tm, __shfl_xor_sync(0xffffffff, tm, 2));
            float nm = fmaxf(m0, tm);
            float s = 0.f;
            #pragma unroll
            for (int c = 0; c < 16; c++) {
                float p = __expf(pr[c] - nm);
                pr[c] = p;
                s += p;
            }
            s += __shfl_xor_sync(0xffffffff, s, 1);
            s += __shfl_xor_sync(0xffffffff, s, 2);
            if (sseg == 0) {
                float corr = __expf(m0 - nm);
                row_sum[srow]  = row_sum[srow] * corr + s;
                row_max[srow]  = nm;
                row_corr[srow] = corr;
            }
        }
        __syncthreads();

        // rescale + acc += P @ V
        {
            int r0 = wm * 16 + (lane >> 2);
            float c0 = row_corr[r0], c1 = row_corr[r0 + 8];
            #pragma unroll
            for (int nt = 0; nt < 4; nt++) {
                acc[nt][0] *= c0; acc[nt][1] *= c0;
                acc[nt][2] *= c1; acc[nt][3] *= c1;
            }
        }
        #pragma unroll
        for (int ks = 0; ks < 8; ks++) {
            int kb = ks * 8 + (lane & 3);
            uint32_t afr[4], bfr[4][2];
            int r0 = wm * 16 + (lane >> 2);
            afr[0] = __float_as_uint(Ps[r0 * ATT_LD + kb]);
            afr[1] = __float_as_uint(Ps[(r0 + 8) * ATT_LD + kb]);
            afr[2] = __float_as_uint(Ps[r0 * ATT_LD + kb + 4]);
            afr[3] = __float_as_uint(Ps[(r0 + 8) * ATT_LD + kb + 4]);
            #pragma unroll
            for (int nt = 0; nt < 4; nt++) {
                int d0 = wn * 32 + nt * 8 + (lane >> 2);
                bfr[nt][0] = __float_as_uint(Vt[d0 * ATT_LD + kb]);
                bfr[nt][1] = __float_as_uint(Vt[d0 * ATT_LD + kb + 4]);
            }
            #pragma unroll
            for (int nt = 0; nt < 4; nt++)
                mma1688(acc[nt], afr, bfr[nt]);
        }
        __syncthreads();
    }

    {
        int r0 = wm * 16 + (lane >> 2);
        float i0 = 1.f / row_sum[r0], i1 = 1.f / row_sum[r0 + 8];
        #pragma unroll
        for (int nt = 0; nt < 4; nt++) {
            int c0 = wn * 32 + nt * 8 + (lane & 3) * 2;
            size_t ra = ((size_t)(b * SS + q0 + r0)) * DD + h * HD + c0;
            size_t rb = ((size_t)(b * SS + q0 + r0 + 8)) * DD + h * HD + c0;
            o[ra]     = f2tf32(acc[nt][0] * i0);
            o[ra + 1] = f2tf32(acc[nt][1] * i0);
            o[rb]     = f2tf32(acc[nt][2] * i1);
            o[rb + 1] = f2tf32(acc[nt][3] * i1);
        }
    }
}

// ---------------- cross attention (windowed, <=9 keys) ----------------
__global__ void cross_attn_kernel(const float* __restrict__ qc, const float* __restrict__ kc,
                                  const float* __restrict__ vc, const int* __restrict__ seg_ids,
                                  float* __restrict__ oc) {
    int n = blockIdx.x;
    int warp = threadIdx.x / 32;
    int lane = threadIdx.x % 32;
    int h = blockIdx.y * 4 + warp;
    int b = n / SS;
    int seg = seg_ids[n];
    int jlo = seg - 8; if (jlo < 0) jlo = 0;
    int cnt = seg - jlo + 1;

    const float* qv = qc + (size_t)n * DD + h * HD;
    float q0v = qv[lane], q1v = qv[lane + 32];

    float sc[9];
    float mx = -INFINITY;
    for (int t = 0; t < cnt; t++) {
        const float* kv = kc + ((size_t)(b * MM + jlo + t)) * DD + h * HD;
        float p = q0v * kv[lane] + q1v * kv[lane + 32];
        #pragma unroll
        for (int off = 16; off > 0; off >>= 1)
            p += __shfl_xor_sync(0xffffffff, p, off);
        p *= 0.125f;
        sc[t] = p;
        mx = fmaxf(mx, p);
    }
    float sum = 0.f;
    for (int t = 0; t < cnt; t++) { sc[t] = __expf(sc[t] - mx); sum += sc[t]; }
    float o0 = 0.f, o1 = 0.f;
    for (int t = 0; t < cnt; t++) {
        const float* vv = vc + ((size_t)(b * MM + jlo + t)) * DD + h * HD;
        o0 += sc[t] * vv[lane];
        o1 += sc[t] * vv[lane + 32];
    }
    float inv = 1.f / sum;
    oc[(size_t)n * DD + h * HD + lane]      = f2tf32(o0 * inv);
    oc[(size_t)n * DD + h * HD + lane + 32] = f2tf32(o1 * inv);
}

// ---------------- silu(g)*u (tf32-rounded out) ----------------
__global__ void silu_mul_kernel(float* __restrict__ g, const float* __restrict__ u, int n) {
    int i = blockIdx.x * blockDim.x + threadIdx.x;
    if (i < n) {
        float gv = g[i];
        float s = gv / (1.f + __expf(-gv));
        g[i] = f2tf32(s * u[i]);
    }
}

// ---------------- launch ----------------
static inline dim3 tg_grid(int M, int N) { return dim3((N + BNN - 1) / BNN, M / BMM); }
#define TG_SMEM (STG * 2 * STAGE_F * (int)sizeof(float))

extern "C" void kernel_launch(void* const* d_in, const int* in_sizes, int n_in,
                              void* d_out, int out_size) {
    const float* x        = (const float*)d_in[0];
    const float* memory   = (const float*)d_in[1];
    const int*   seg_ids  = (const int*)  d_in[2];
    const float* norm1_w  = (const float*)d_in[3];
    const float* W_dq     = (const float*)d_in[4];
    const float* W_uq     = (const float*)d_in[5];
    const float* W_dkv    = (const float*)d_in[6];
    const float* W_uk     = (const float*)d_in[7];
    const float* W_uv     = (const float*)d_in[8];
    const float* W_o_self = (const float*)d_in[9];
    const float* norm2_w  = (const float*)d_in[10];
    const float* W_q_c    = (const float*)d_in[11];
    const float* W_k_c    = (const float*)d_in[12];
    const float* W_v_c    = (const float*)d_in[13];
    const float* W_o_c    = (const float*)d_in[14];
    const float* norm3_w  = (const float*)d_in[15];
    const float* W_gate   = (const float*)d_in[16];
    const float* W_up     = (const float*)d_in[17];
    const float* W_down   = (const float*)d_in[18];
    float* out = (float*)d_out;

    float *h, *tq, *q, *ckv, *k, *v, *o, *x1, *h2, *qc, *kc, *vc, *oc, *x2, *h3, *gate, *up, *mem;
    cudaGetSymbolAddress((void**)&h,   g_h);
    cudaGetSymbolAddress((void**)&tq,  g_tq);
    cudaGetSymbolAddress((void**)&q,   g_q);
    cudaGetSymbolAddress((void**)&ckv, g_ckv);
    cudaGetSymbolAddress((void**)&k,   g_k);
    cudaGetSymbolAddress((void**)&v,   g_v);
    cudaGetSymbolAddress((void**)&o,   g_o);
    cudaGetSymbolAddress((void**)&x1,  g_x1);
    cudaGetSymbolAddress((void**)&h2,  g_h2);
    cudaGetSymbolAddress((void**)&qc,  g_qc);
    cudaGetSymbolAddress((void**)&kc,  g_kc);
    cudaGetSymbolAddress((void**)&vc,  g_vc);
    cudaGetSymbolAddress((void**)&oc,  g_oc);
    cudaGetSymbolAddress((void**)&x2,  g_x2);
    cudaGetSymbolAddress((void**)&h3,  g_h3);
    cudaGetSymbolAddress((void**)&gate,g_gate);
    cudaGetSymbolAddress((void**)&up,  g_up);
    cudaGetSymbolAddress((void**)&mem, g_mem);

    float *w_dq, *w_uq, *w_dkv, *w_uk, *w_uv, *w_oself, *w_qc, *w_kc, *w_vc, *w_oc,
          *w_gate, *w_up, *w_down;
    cudaGetSymbolAddress((void**)&w_dq,    gw_dq);
    cudaGetSymbolAddress((void**)&w_uq,    gw_uq);
    cudaGetSymbolAddress((void**)&w_dkv,   gw_dkv);
    cudaGetSymbolAddress((void**)&w_uk,    gw_uk);
    cudaGetSymbolAddress((void**)&w_uv,    gw_uv);
    cudaGetSymbolAddress((void**)&w_oself, gw_oself);
    cudaGetSymbolAddress((void**)&w_qc,    gw_qc);
    cudaGetSymbolAddress((void**)&w_kc,    gw_kc);
    cudaGetSymbolAddress((void**)&w_vc,    gw_vc);
    cudaGetSymbolAddress((void**)&w_oc,    gw_oc);
    cudaGetSymbolAddress((void**)&w_gate,  gw_gate);
    cudaGetSymbolAddress((void**)&w_up,    gw_up);
    cudaGetSymbolAddress((void**)&w_down,  gw_down);

    // fused convert table
    WTable wt;
    const float* srcs[13] = {W_dq, W_uq, W_dkv, W_uk, W_uv, W_o_self, W_q_c, W_k_c, W_v_c,
                             W_o_c, W_gate, W_up, W_down};
    float* dsts[13] = {w_dq, w_uq, w_dkv, w_uk, w_uv, w_oself, w_qc, w_kc, w_vc,
                       w_oc, w_gate, w_up, w_down};
    int Ks[13] = {DD, 32, DD, 64, 64, DD, DD, DD, DD, DD, DD, DD, FF};
    int Ns[13] = {32, DD, 64, DD, DD, DD, DD, DD, DD, DD, FF, FF, DD};
    int tot = 0;
    for (int i = 0; i < 13; i++) {
        wt.w[i].src = srcs[i]; wt.w[i].dst = dsts[i];
        wt.w[i].K = Ks[i]; wt.w[i].N = Ns[i];
        wt.w[i].tile0 = tot;
        tot += (Ks[i] / 32) * (Ns[i] / 32);
    }
    convert_all_kernel<<<tot, 256>>>(wt);
    round_copy_kernel<<<(MTOK * DD + 255) / 256, 256>>>(memory, mem, MTOK * DD);

    cudaFuncSetAttribute(tgemm_kernel, cudaFuncAttributeMaxDynamicSharedMemorySize, TG_SMEM);
    int attn_smem = (4 * 64 * ATT_LD + 3 * 64) * sizeof(float);
    cudaFuncSetAttribute(self_attn_kernel, cudaFuncAttributeMaxDynamicSharedMemorySize, attn_smem);

    // ---- Phase 1: MLA self-attention ----
    rmsnorm_kernel<<<NTOK, 256>>>(x, norm1_w, h, DD);
    tgemm_kernel<<<tg_grid(NTOK, 32),  256, TG_SMEM>>>(h,   w_dq,  nullptr, tq,  NTOK, 32,  DD, 1);
    tgemm_kernel<<<tg_grid(NTOK, DD),  256, TG_SMEM>>>(tq,  w_uq,  nullptr, q,   NTOK, DD,  32, 1);
    tgemm_kernel<<<tg_grid(NTOK, 64),  256, TG_SMEM>>>(h,   w_dkv, nullptr, ckv, NTOK, 64,  DD, 1);
    tgemm_kernel<<<tg_grid(NTOK, DD),  256, TG_SMEM>>>(ckv, w_uk,  nullptr, k,   NTOK, DD,  64, 1);
    tgemm_kernel<<<tg_grid(NTOK, DD),  256, TG_SMEM>>>(ckv, w_uv,  nullptr, v,   NTOK, DD,  64, 1);
    self_attn_kernel<<<dim3(SS / 64, HH, BB), 256, attn_smem>>>(q, k, v, o);
    tgemm_kernel<<<tg_grid(NTOK, DD),  256, TG_SMEM>>>(o, w_oself, x, x1, NTOK, DD, DD, 0);

    // ---- Phase 2: windowed cross-attention ----
    rmsnorm_kernel<<<NTOK, 256>>>(x1, norm2_w, h2, DD);
    tgemm_kernel<<<tg_grid(NTOK, DD), 256, TG_SMEM>>>(h2,  w_qc, nullptr, qc, NTOK, DD, DD, 0);
    tgemm_kernel<<<tg_grid(MTOK, DD), 256, TG_SMEM>>>(mem, w_kc, nullptr, kc, MTOK, DD, DD, 0);
    tgemm_kernel<<<tg_grid(MTOK, DD), 256, TG_SMEM>>>(mem, w_vc, nullptr, vc, MTOK, DD, DD, 0);
    cross_attn_kernel<<<dim3(NTOK, 4), 128>>>(qc, kc, vc, seg_ids, oc);
    tgemm_kernel<<<tg_grid(NTOK, DD), 256, TG_SMEM>>>(oc, w_oc, x1, x2, NTOK, DD, DD, 0);

    // ---- Phase 3: SwiGLU MLP ----
    rmsnorm_kernel<<<NTOK, 256>>>(x2, norm3_w, h3, DD);
    tgemm_kernel<<<tg_grid(NTOK, FF), 256, TG_SMEM>>>(h3, w_gate, nullptr, gate, NTOK, FF, DD, 0);
    tgemm_kernel<<<tg_grid(NTOK, FF), 256, TG_SMEM>>>(h3, w_up,   nullptr, up,   NTOK, FF, DD, 0);
    silu_mul_kernel<<<(NTOK * FF + 255) / 256, 256>>>(gate, up, NTOK * FF);
    tgemm_kernel<<<tg_grid(NTOK, DD), 256, TG_SMEM>>>(gate, w_down, x2, out, NTOK, DD, FF, 0);
}